// round 4
// baseline (speedup 1.0000x reference)
#include <cuda_runtime.h>

// AEC frequency-domain dual-filter IPNLMS, round 4 = round 2 (best) with the
// frame body made fully branchless: no __any_sync votes, no runtime if{} —
// renorm via unconditional fmin(1, 2*rsqrt), recovery via per-tap selects,
// prefetch via min-clamp. 2 lanes/bin, unroll x10, 9 blocks x 32 threads.

namespace {
constexpr int F_BINS   = 129;
constexpr int T_FRAMES = 2000;
constexpr int NF       = 16000;          // B*T, serial frame order (t, b)
constexpr int TF       = T_FRAMES * F_BINS;
}

__device__ __forceinline__ float pair_sum(float v) {
    return v + __shfl_xor_sync(0xffffffffu, v, 1);
}

__global__ void __launch_bounds__(32, 1)
aec_ipnlms4(const float* __restrict__ mic_r, const float* __restrict__ mic_i,
            const float* __restrict__ ref_r, const float* __restrict__ ref_i,
            const float* __restrict__ fir_r0, const float* __restrict__ fir_i0,
            const float* __restrict__ adf_r0, const float* __restrict__ adf_i0,
            float2* __restrict__ out)
{
    const float LAM = 0.97f;
    const float OML = (float)(1.0 - 0.97);   // match python double-derived constant

    const int lane = threadIdx.x;
    const int gid  = blockIdx.x * 32 + lane;
    const int bin  = gid >> 1;
    const int half = gid & 1;                 // 0: taps 0-4, 1: taps 5-9
    const bool writer = (half == 0) && (bin < F_BINS);
    const int f = (bin < F_BINS) ? bin : (F_BINS - 1);   // shadow lanes track bin 128
    const bool low = (f <= 35);               // 10-tap window, else 8-tap
    const float m89   = low ? 1.0f : 0.0f;    // mask for global taps 8,9
    const float c0    = low ? 0.025f : 0.03125f;   // (1-ALPHA)/(2*nblocks)
    const float mtail = half ? m89 : 1.0f;    // mask on this lane's taps j=3,4

    // ---- register state: 5 taps per lane ----
    float Hr[5], Hi[5], cfr[5], cfi[5], car[5], cai[5], mg2[5];
    float s_loc = 0.0f;
#pragma unroll
    for (int j = 0; j < 5; ++j) {
        const int k = half * 5 + j;
        const float mk = (k < 8) ? 1.0f : m89;  // zero masked taps (output-equivalent)
        Hr[j] = 0.0f; Hi[j] = 0.0f;
        cfr[j] = fir_r0[f * 10 + k] * mk;  cfi[j] = fir_i0[f * 10 + k] * mk;
        car[j] = adf_r0[f * 10 + k] * mk;  cai[j] = adf_i0[f * 10 + k] * mk;
        mg2[j] = car[j] * car[j] + cai[j] * cai[j];
        s_loc += mg2[j];
    }
    float s_sum  = pair_sum(s_loc);           // carried Σ|a|^2 (pre-1e-10)
    float invs15 = __fdividef(1.5f, s_sum + 1e-10f);
    float mse_in = 1.0f, mse_ad = 1.0f, mse_mn = 1.0f;

    // ---- 2-deep prefetch pipeline (data + offsets, ping-pong) ----
    float pmr[2], pmi[2], prr[2], pri[2];
    int poff[2] = { f, TF + f };              // off(n) = b*T*F + t*F + f
    pmr[0] = mic_r[poff[0]]; pmi[0] = mic_i[poff[0]];
    prr[0] = ref_r[poff[0]]; pri[0] = ref_i[poff[0]];
    pmr[1] = mic_r[poff[1]]; pmi[1] = mic_i[poff[1]];
    prr[1] = ref_r[poff[1]]; pri[1] = ref_i[poff[1]];

    for (int n0 = 0; n0 < NF; n0 += 10) {
#pragma unroll
        for (int u = 0; u < 10; ++u) {        // compile-time u
            const int n  = n0 + u;
            const int sl = u & 1;
            const float mr_f = pmr[sl], mi_f = pmi[sl];
            const float rr_f = prr[sl], ri_f = pri[sl];
            const int ooff = poff[sl];

            // ---- prefetch frame n+2 (branchless: clamp to last frame) ----
            {
                const int n2 = (n + 2 < NF) ? (n + 2) : (NF - 1);
                const int off = (n2 & 7) * TF + (n2 >> 3) * F_BINS + f;
                poff[sl] = off;
                pmr[sl] = __ldg(mic_r + off); pmi[sl] = __ldg(mic_i + off);
                prr[sl] = __ldg(ref_r + off); pri[sl] = __ldg(ref_i + off);
            }

            // ---- history rotation: tap j lives in slot (j-u) mod 5 ----
            const int ins = (10 - u) % 5;
            const float xr = __shfl_xor_sync(0xffffffffu, Hr[ins], 1);
            const float xi = __shfl_xor_sync(0xffffffffu, Hi[ins], 1);
            Hr[ins] = half ? xr : rr_f;
            Hi[ins] = half ? xi : ri_f;

            // ---- dual-filter echo estimates ----
            float fer = 0.f, fei = 0.f, aer = 0.f, aei = 0.f;
#pragma unroll
            for (int j = 0; j < 5; ++j) {
                const int p = ((j - u) % 5 + 5) % 5;
                const float hr = Hr[p], hi = Hi[p];
                fer += cfr[j] * hr + cfi[j] * hi;
                fei += cfr[j] * hi - cfi[j] * hr;
                aer += car[j] * hr + cai[j] * hi;
                aei += car[j] * hi - cai[j] * hr;
            }
            fer = pair_sum(fer); fei = pair_sum(fei);
            aer = pair_sum(aer); aei = pair_sum(aei);

            const float feR = mr_f - fer, feI = mi_f - fei;
            const float aeR = mr_f - aer, aeI = mi_f - aei;
            const float f_pow = feR * feR + feI * feI;
            const float a_pow = aeR * aeR + aeI * aeI;
            const bool selA = (f_pow >= a_pow);
            const float errR = selA ? aeR : feR;
            const float errI = selA ? aeI : feI;

            // ---- MSE smoothing + control flags ----
            mse_in = LAM * mse_in + OML * (mr_f * mr_f + mi_f * mi_f);
            mse_mn = LAM * mse_mn + OML * f_pow;
            mse_ad = LAM * mse_ad + OML * a_pow;
            const float gate = (mse_ad > mse_in * 8.0f) ? 0.0f : 1.0f;
            const bool rec = (mse_in > mse_mn * 8.0f) && (mse_mn < 0.5f * mse_ad);

            // ---- masked reference power ----
            float tl = 0.f, tt = 0.f;
#pragma unroll
            for (int j = 0; j < 5; ++j) {
                const int p = ((j - u) % 5 + 5) % 5;
                const float v = Hr[p] * Hr[p] + Hi[p] * Hi[p];
                if (j < 3) tl += v; else tt += v;
            }
            tl += mtail * tt;
            const float tot  = pair_sum(tl);
            const float mu_n = __fdividef(0.5f, (tot + 1e-8f) + 1e-10f);
            const float mug  = mu_n * gate;          // gate in {0,1} folds through clip
            const float A  = mug * c0;
            const float B  = mug * invs15;
            const float At = A * mtail;              // mask folds through clip
            const float Bt = B * mtail;

            // ---- IPNLMS update + branchless MAX_COEF renorm ----
#pragma unroll
            for (int j = 0; j < 5; ++j) {
                const int p = ((j - u) % 5 + 5) % 5;
                const float hr = Hr[p], hi = Hi[p];
                const float g2 = (j >= 3) ? (At + mg2[j] * Bt) : (A + mg2[j] * B);
                const float p_r = hr * aeR + hi * aeI;
                const float p_i = hi * aeR - hr * aeI;
                const float ur = fminf(fmaxf(g2 * p_r, -0.01f), 0.01f);
                const float ui = fminf(fmaxf(g2 * p_i, -0.01f), 0.01f);
                car[j] += ur; cai[j] += ui;
                // renorm scale: exactly 1.0 when |c|<=2, else ~2/|c|
                const float m2 = car[j] * car[j] + cai[j] * cai[j];
                const float sc = fminf(1.0f, 2.0f * rsqrtf(m2 + 1e-10f));
                car[j] *= sc; cai[j] *= sc;
            }

            // ---- copy adaptive -> main, then branchless recovery ----
            float s_new = 0.f;
#pragma unroll
            for (int j = 0; j < 5; ++j) {
                cfr[j] = selA ? car[j] : cfr[j];
                cfi[j] = selA ? cai[j] : cfi[j];
                car[j] = rec ? cfr[j] : car[j];
                cai[j] = rec ? cfi[j] : cai[j];
                mg2[j] = car[j] * car[j] + cai[j] * cai[j];
                s_new += mg2[j];
            }
            s_sum  = pair_sum(s_new);
            invs15 = __fdividef(1.5f, s_sum + 1e-10f);   // for next frame's B

            // ---- NLP every 10th frame (compile-time slot) ----
            float o_r = errR, o_i = errI;
            if (u == 0) {
                const float echR = selA ? aer : fer;
                const float echI = selA ? aei : fei;
                const float em = sqrtf(errR * errR + errI * errI + 1e-12f);
                const float cm = sqrtf(echR * echR + echI * echI);
                const float supp = fmaxf(em - 1.5f * cm, 0.01f * em);
                const float g = supp / em;
                o_r = g * errR; o_i = g * errI;
            }

            if (writer) out[ooff] = make_float2(o_r, o_i);
        }
    }
}

extern "C" void kernel_launch(void* const* d_in, const int* in_sizes, int n_in,
                              void* d_out, int out_size) {
    (void)in_sizes; (void)n_in; (void)out_size;
    aec_ipnlms4<<<9, 32>>>(
        (const float*)d_in[0], (const float*)d_in[1],
        (const float*)d_in[2], (const float*)d_in[3],
        (const float*)d_in[4], (const float*)d_in[5],
        (const float*)d_in[6], (const float*)d_in[7],
        (float2*)d_out);
}

// round 5
// speedup vs baseline: 1.3581x; 1.3581x over previous
#include <cuda_runtime.h>

// AEC frequency-domain dual-filter IPNLMS, round 5 = round 2 (best, 6525us)
// with exactly two changes:
//  (1) renorm vote hoisted to frame top on carried s_sum (threshold 3.8 is a
//      proven-exact skip bound given the 0.01 update clip); recovery by SELs.
//  (2) tree-structured estimate accumulators (MAC chain 40 -> 24 cyc).
// 2 lanes/bin (taps 5+5), frame loop unrolled x10, 9 blocks x 32 threads.

namespace {
constexpr int F_BINS   = 129;
constexpr int T_FRAMES = 2000;
constexpr int NF       = 16000;          // B*T, serial frame order (t, b)
constexpr int TF       = T_FRAMES * F_BINS;
}

__device__ __forceinline__ float pair_sum(float v) {
    return v + __shfl_xor_sync(0xffffffffu, v, 1);
}

__global__ void __launch_bounds__(32, 1)
aec_ipnlms5(const float* __restrict__ mic_r, const float* __restrict__ mic_i,
            const float* __restrict__ ref_r, const float* __restrict__ ref_i,
            const float* __restrict__ fir_r0, const float* __restrict__ fir_i0,
            const float* __restrict__ adf_r0, const float* __restrict__ adf_i0,
            float2* __restrict__ out)
{
    const float LAM = 0.97f;
    const float OML = (float)(1.0 - 0.97);   // match python double-derived constant

    const int lane = threadIdx.x;
    const int gid  = blockIdx.x * 32 + lane;
    const int bin  = gid >> 1;
    const int half = gid & 1;                 // 0: taps 0-4, 1: taps 5-9
    const bool writer = (half == 0) && (bin < F_BINS);
    const int f = (bin < F_BINS) ? bin : (F_BINS - 1);   // shadow lanes track bin 128
    const bool low = (f <= 35);               // 10-tap window, else 8-tap
    const float m89   = low ? 1.0f : 0.0f;    // mask for global taps 8,9
    const float c0    = low ? 0.025f : 0.03125f;   // (1-ALPHA)/(2*nblocks)
    const float mtail = half ? m89 : 1.0f;    // mask on this lane's taps j=3,4

    // ---- register state: 5 taps per lane ----
    float Hr[5], Hi[5], cfr[5], cfi[5], car[5], cai[5], mg2[5];
    float s_loc = 0.0f;
#pragma unroll
    for (int j = 0; j < 5; ++j) {
        const int k = half * 5 + j;
        const float mk = (k < 8) ? 1.0f : m89;  // zero masked taps (output-equivalent)
        Hr[j] = 0.0f; Hi[j] = 0.0f;
        cfr[j] = fir_r0[f * 10 + k] * mk;  cfi[j] = fir_i0[f * 10 + k] * mk;
        car[j] = adf_r0[f * 10 + k] * mk;  cai[j] = adf_i0[f * 10 + k] * mk;
        mg2[j] = car[j] * car[j] + cai[j] * cai[j];
        s_loc += mg2[j];
    }
    float s_sum  = pair_sum(s_loc);           // carried Σ|a|^2 (post-frame value)
    float invs15 = __fdividef(1.5f, s_sum + 1e-10f);
    float mse_in = 1.0f, mse_ad = 1.0f, mse_mn = 1.0f;

    // ---- 2-deep prefetch pipeline (data + offsets, ping-pong) ----
    float pmr[2], pmi[2], prr[2], pri[2];
    int poff[2] = { f, TF + f };              // off(n) = b*T*F + t*F + f
    pmr[0] = mic_r[poff[0]]; pmi[0] = mic_i[poff[0]];
    prr[0] = ref_r[poff[0]]; pri[0] = ref_i[poff[0]];
    pmr[1] = mic_r[poff[1]]; pmi[1] = mic_i[poff[1]];
    prr[1] = ref_r[poff[1]]; pri[1] = ref_i[poff[1]];

    for (int n0 = 0; n0 < NF; n0 += 10) {
#pragma unroll
        for (int u = 0; u < 10; ++u) {        // compile-time u
            const int n  = n0 + u;
            const int sl = u & 1;
            const float mr_f = pmr[sl], mi_f = pmi[sl];
            const float rr_f = prr[sl], ri_f = pri[sl];
            const int ooff = poff[sl];

            // ---- renorm vote at frame TOP on carried s_sum (one frame old).
            // s_prev < 3.8  =>  s_now < 4 (0.01-clip growth bound)  =>  every
            // per-tap renorm scale is exactly 1  =>  skipping is bit-exact.
            const bool need_rn = __any_sync(0xffffffffu, s_sum >= 3.8f);

            // ---- prefetch frame n+2 ----
            {
                const int n2 = n + 2;
                if (n2 < NF) {
                    const int off = (n2 & 7) * TF + (n2 >> 3) * F_BINS + f;
                    poff[sl] = off;
                    pmr[sl] = __ldg(mic_r + off); pmi[sl] = __ldg(mic_i + off);
                    prr[sl] = __ldg(ref_r + off); pri[sl] = __ldg(ref_i + off);
                }
            }

            // ---- history rotation: tap j lives in slot (j-u) mod 5 ----
            const int ins = (10 - u) % 5;
            const float xr = __shfl_xor_sync(0xffffffffu, Hr[ins], 1);
            const float xi = __shfl_xor_sync(0xffffffffu, Hi[ins], 1);
            Hr[ins] = half ? xr : rr_f;
            Hi[ins] = half ? xi : ri_f;

            // ---- dual-filter echo estimates (tree accumulators) ----
            float ferA = 0.f, ferB = 0.f, feiA = 0.f, feiB = 0.f;
            float aerA = 0.f, aerB = 0.f, aeiA = 0.f, aeiB = 0.f;
#pragma unroll
            for (int j = 0; j < 5; ++j) {
                const int p = ((j - u) % 5 + 5) % 5;
                const float hr = Hr[p], hi = Hi[p];
                ferA += cfr[j] * hr;  ferB += cfi[j] * hi;
                feiA += cfr[j] * hi;  feiB -= cfi[j] * hr;
                aerA += car[j] * hr;  aerB += cai[j] * hi;
                aeiA += car[j] * hi;  aeiB -= cai[j] * hr;
            }
            const float fer = pair_sum(ferA + ferB);
            const float fei = pair_sum(feiA + feiB);
            const float aer = pair_sum(aerA + aerB);
            const float aei = pair_sum(aeiA + aeiB);

            const float feR = mr_f - fer, feI = mi_f - fei;
            const float aeR = mr_f - aer, aeI = mi_f - aei;
            const float f_pow = feR * feR + feI * feI;
            const float a_pow = aeR * aeR + aeI * aeI;
            const bool selA = (f_pow >= a_pow);
            const float errR = selA ? aeR : feR;
            const float errI = selA ? aeI : feI;

            // ---- MSE smoothing + control flags ----
            mse_in = LAM * mse_in + OML * (mr_f * mr_f + mi_f * mi_f);
            mse_mn = LAM * mse_mn + OML * f_pow;
            mse_ad = LAM * mse_ad + OML * a_pow;
            const float gate = (mse_ad > mse_in * 8.0f) ? 0.0f : 1.0f;
            const bool rec = (mse_in > mse_mn * 8.0f) && (mse_mn < 0.5f * mse_ad);

            // ---- masked reference power ----
            float tl = 0.f, tt = 0.f;
#pragma unroll
            for (int j = 0; j < 5; ++j) {
                const int p = ((j - u) % 5 + 5) % 5;
                const float v = Hr[p] * Hr[p] + Hi[p] * Hi[p];
                if (j < 3) tl += v; else tt += v;
            }
            tl += mtail * tt;
            const float tot  = pair_sum(tl);
            const float mu_n = __fdividef(0.5f, (tot + 1e-8f) + 1e-10f);
            const float mug  = mu_n * gate;          // gate in {0,1} folds through clip
            const float A  = mug * c0;
            const float B  = mug * invs15;
            const float At = A * mtail;              // mask folds through clip
            const float Bt = B * mtail;

            // ---- IPNLMS update ----
#pragma unroll
            for (int j = 0; j < 5; ++j) {
                const int p = ((j - u) % 5 + 5) % 5;
                const float hr = Hr[p], hi = Hi[p];
                const float g2 = (j >= 3) ? (At + mg2[j] * Bt) : (A + mg2[j] * B);
                const float p_r = hr * aeR + hi * aeI;
                const float p_i = hi * aeR - hr * aeI;
                const float ur = fminf(fmaxf(g2 * p_r, -0.01f), 0.01f);
                const float ui = fminf(fmaxf(g2 * p_i, -0.01f), 0.01f);
                car[j] += ur; cai[j] += ui;
            }

            // ---- rare exact MAX_COEF renorm (predicate ready since frame top) ----
            if (need_rn) {
#pragma unroll
                for (int j = 0; j < 5; ++j) {
                    const float m2 = car[j] * car[j] + cai[j] * cai[j];
                    const float mg = sqrtf(m2 + 1e-10f);
                    const float sc = (mg > 2.0f) ? (2.0f / mg) : 1.0f;
                    car[j] *= sc; cai[j] *= sc;
                }
            }

            // ---- copy adaptive -> main, recovery via SELs; refresh mg2 / s ----
            float s_new = 0.f;
#pragma unroll
            for (int j = 0; j < 5; ++j) {
                cfr[j] = selA ? car[j] : cfr[j];
                cfi[j] = selA ? cai[j] : cfi[j];
                car[j] = rec ? cfr[j] : car[j];
                cai[j] = rec ? cfi[j] : cai[j];
                mg2[j] = car[j] * car[j] + cai[j] * cai[j];
                s_new += mg2[j];
            }
            s_sum  = pair_sum(s_new);
            invs15 = __fdividef(1.5f, s_sum + 1e-10f);   // for next frame's B

            // ---- NLP every 10th frame (compile-time slot) ----
            float o_r = errR, o_i = errI;
            if (u == 0) {
                const float echR = selA ? aer : fer;
                const float echI = selA ? aei : fei;
                const float em = sqrtf(errR * errR + errI * errI + 1e-12f);
                const float cm = sqrtf(echR * echR + echI * echI);
                const float supp = fmaxf(em - 1.5f * cm, 0.01f * em);
                const float g = supp / em;
                o_r = g * errR; o_i = g * errI;
            }

            if (writer) out[ooff] = make_float2(o_r, o_i);
        }
    }
}

extern "C" void kernel_launch(void* const* d_in, const int* in_sizes, int n_in,
                              void* d_out, int out_size) {
    (void)in_sizes; (void)n_in; (void)out_size;
    aec_ipnlms5<<<9, 32>>>(
        (const float*)d_in[0], (const float*)d_in[1],
        (const float*)d_in[2], (const float*)d_in[3],
        (const float*)d_in[4], (const float*)d_in[5],
        (const float*)d_in[6], (const float*)d_in[7],
        (float2*)d_out);
}

// round 6
// speedup vs baseline: 1.5536x; 1.1439x over previous
#include <cuda_runtime.h>

// AEC frequency-domain dual-filter IPNLMS, round 6 = round 5 (best, 5942us)
// with the hot 10-frame body made a single branch-free basic block:
//  (1) renorm decision hoisted to once per 10-frame block (exact-skip proof:
//      0.01 update clip + copies never raise |c|; s<3.24 && sf<3.24 at block
//      start => all |c| < 1.9414 < 2 for the whole block => scales all == 1).
//      Rare slow block does the exact per-frame renorm.
//  (2) branchless prefetch (offset clamped to last frame).
// 2 lanes/bin (taps 5+5), 9 blocks x 32 threads.

namespace {
constexpr int F_BINS   = 129;
constexpr int T_FRAMES = 2000;
constexpr int NF       = 16000;          // B*T, serial frame order (t, b)
constexpr int TF       = T_FRAMES * F_BINS;
}

__device__ __forceinline__ float pair_sum(float v) {
    return v + __shfl_xor_sync(0xffffffffu, v, 1);
}

struct St {
    float Hr[5], Hi[5], cfr[5], cfi[5], car[5], cai[5], mg2[5];
    float s_sum, invs15, mse_in, mse_ad, mse_mn;
    float pmr[2], pmi[2], prr[2], pri[2];
    int   poff[2];
};

template<bool RENORM>
__device__ __forceinline__ void run_block(
    St& st, int n0, int f, int half, bool writer,
    float mtail, float c0,
    const float* __restrict__ mic_r, const float* __restrict__ mic_i,
    const float* __restrict__ ref_r, const float* __restrict__ ref_i,
    float2* __restrict__ out)
{
    const float LAM = 0.97f;
    const float OML = (float)(1.0 - 0.97);

#pragma unroll
    for (int u = 0; u < 10; ++u) {            // compile-time u
        const int n  = n0 + u;
        const int sl = u & 1;
        const float mr_f = st.pmr[sl], mi_f = st.pmi[sl];
        const float rr_f = st.prr[sl], ri_f = st.pri[sl];
        const int ooff = st.poff[sl];

        // ---- prefetch frame n+2 (branchless clamp) ----
        {
            const int n2 = (n + 2 < NF) ? (n + 2) : (NF - 1);
            const int off = (n2 & 7) * TF + (n2 >> 3) * F_BINS + f;
            st.poff[sl] = off;
            st.pmr[sl] = __ldg(mic_r + off); st.pmi[sl] = __ldg(mic_i + off);
            st.prr[sl] = __ldg(ref_r + off); st.pri[sl] = __ldg(ref_i + off);
        }

        // ---- history rotation: tap j lives in slot (j-u) mod 5 ----
        const int ins = (10 - u) % 5;
        const float xr = __shfl_xor_sync(0xffffffffu, st.Hr[ins], 1);
        const float xi = __shfl_xor_sync(0xffffffffu, st.Hi[ins], 1);
        st.Hr[ins] = half ? xr : rr_f;
        st.Hi[ins] = half ? xi : ri_f;

        // ---- dual-filter echo estimates (tree accumulators) ----
        float ferA = 0.f, ferB = 0.f, feiA = 0.f, feiB = 0.f;
        float aerA = 0.f, aerB = 0.f, aeiA = 0.f, aeiB = 0.f;
#pragma unroll
        for (int j = 0; j < 5; ++j) {
            const int p = ((j - u) % 5 + 5) % 5;
            const float hr = st.Hr[p], hi = st.Hi[p];
            ferA += st.cfr[j] * hr;  ferB += st.cfi[j] * hi;
            feiA += st.cfr[j] * hi;  feiB -= st.cfi[j] * hr;
            aerA += st.car[j] * hr;  aerB += st.cai[j] * hi;
            aeiA += st.car[j] * hi;  aeiB -= st.cai[j] * hr;
        }
        const float fer = pair_sum(ferA + ferB);
        const float fei = pair_sum(feiA + feiB);
        const float aer = pair_sum(aerA + aerB);
        const float aei = pair_sum(aeiA + aeiB);

        const float feR = mr_f - fer, feI = mi_f - fei;
        const float aeR = mr_f - aer, aeI = mi_f - aei;
        const float f_pow = feR * feR + feI * feI;
        const float a_pow = aeR * aeR + aeI * aeI;
        const bool selA = (f_pow >= a_pow);
        const float errR = selA ? aeR : feR;
        const float errI = selA ? aeI : feI;

        // ---- MSE smoothing + control flags ----
        st.mse_in = LAM * st.mse_in + OML * (mr_f * mr_f + mi_f * mi_f);
        st.mse_mn = LAM * st.mse_mn + OML * f_pow;
        st.mse_ad = LAM * st.mse_ad + OML * a_pow;
        const float gate = (st.mse_ad > st.mse_in * 8.0f) ? 0.0f : 1.0f;
        const bool rec = (st.mse_in > st.mse_mn * 8.0f) && (st.mse_mn < 0.5f * st.mse_ad);

        // ---- masked reference power ----
        float tl = 0.f, tt = 0.f;
#pragma unroll
        for (int j = 0; j < 5; ++j) {
            const int p = ((j - u) % 5 + 5) % 5;
            const float v = st.Hr[p] * st.Hr[p] + st.Hi[p] * st.Hi[p];
            if (j < 3) tl += v; else tt += v;
        }
        tl += mtail * tt;
        const float tot  = pair_sum(tl);
        const float mu_n = __fdividef(0.5f, (tot + 1e-8f) + 1e-10f);
        const float mug  = mu_n * gate;           // gate in {0,1} folds through clip
        const float A  = mug * c0;
        const float B  = mug * st.invs15;
        const float At = A * mtail;               // mask folds through clip
        const float Bt = B * mtail;

        // ---- IPNLMS update ----
#pragma unroll
        for (int j = 0; j < 5; ++j) {
            const int p = ((j - u) % 5 + 5) % 5;
            const float hr = st.Hr[p], hi = st.Hi[p];
            const float g2 = (j >= 3) ? (At + st.mg2[j] * Bt) : (A + st.mg2[j] * B);
            const float p_r = hr * aeR + hi * aeI;
            const float p_i = hi * aeR - hr * aeI;
            const float ur = fminf(fmaxf(g2 * p_r, -0.01f), 0.01f);
            const float ui = fminf(fmaxf(g2 * p_i, -0.01f), 0.01f);
            st.car[j] += ur; st.cai[j] += ui;
        }

        // ---- exact MAX_COEF renorm: slow block only ----
        if (RENORM) {
#pragma unroll
            for (int j = 0; j < 5; ++j) {
                const float m2 = st.car[j] * st.car[j] + st.cai[j] * st.cai[j];
                const float mg = sqrtf(m2 + 1e-10f);
                const float sc = (mg > 2.0f) ? (2.0f / mg) : 1.0f;
                st.car[j] *= sc; st.cai[j] *= sc;
            }
        }

        // ---- copy adaptive -> main, recovery via SELs; refresh mg2 / s ----
        float s_new = 0.f;
#pragma unroll
        for (int j = 0; j < 5; ++j) {
            st.cfr[j] = selA ? st.car[j] : st.cfr[j];
            st.cfi[j] = selA ? st.cai[j] : st.cfi[j];
            st.car[j] = rec ? st.cfr[j] : st.car[j];
            st.cai[j] = rec ? st.cfi[j] : st.cai[j];
            st.mg2[j] = st.car[j] * st.car[j] + st.cai[j] * st.cai[j];
            s_new += st.mg2[j];
        }
        st.s_sum  = pair_sum(s_new);
        st.invs15 = __fdividef(1.5f, st.s_sum + 1e-10f);

        // ---- NLP every 10th frame (compile-time slot) ----
        float o_r = errR, o_i = errI;
        if (u == 0) {
            const float echR = selA ? aer : fer;
            const float echI = selA ? aei : fei;
            const float em = sqrtf(errR * errR + errI * errI + 1e-12f);
            const float cm = sqrtf(echR * echR + echI * echI);
            const float supp = fmaxf(em - 1.5f * cm, 0.01f * em);
            const float g = supp / em;
            o_r = g * errR; o_i = g * errI;
        }

        if (writer) out[ooff] = make_float2(o_r, o_i);
    }
}

__global__ void __launch_bounds__(32, 1)
aec_ipnlms6(const float* __restrict__ mic_r, const float* __restrict__ mic_i,
            const float* __restrict__ ref_r, const float* __restrict__ ref_i,
            const float* __restrict__ fir_r0, const float* __restrict__ fir_i0,
            const float* __restrict__ adf_r0, const float* __restrict__ adf_i0,
            float2* __restrict__ out)
{
    const int lane = threadIdx.x;
    const int gid  = blockIdx.x * 32 + lane;
    const int bin  = gid >> 1;
    const int half = gid & 1;                 // 0: taps 0-4, 1: taps 5-9
    const bool writer = (half == 0) && (bin < F_BINS);
    const int f = (bin < F_BINS) ? bin : (F_BINS - 1);
    const bool low = (f <= 35);               // 10-tap window, else 8-tap
    const float m89   = low ? 1.0f : 0.0f;
    const float c0    = low ? 0.025f : 0.03125f;   // (1-ALPHA)/(2*nblocks)
    const float mtail = half ? m89 : 1.0f;

    St st;
    float s_loc = 0.0f;
#pragma unroll
    for (int j = 0; j < 5; ++j) {
        const int k = half * 5 + j;
        const float mk = (k < 8) ? 1.0f : m89;  // zero masked taps (output-equivalent)
        st.Hr[j] = 0.0f; st.Hi[j] = 0.0f;
        st.cfr[j] = fir_r0[f * 10 + k] * mk;  st.cfi[j] = fir_i0[f * 10 + k] * mk;
        st.car[j] = adf_r0[f * 10 + k] * mk;  st.cai[j] = adf_i0[f * 10 + k] * mk;
        st.mg2[j] = st.car[j] * st.car[j] + st.cai[j] * st.cai[j];
        s_loc += st.mg2[j];
    }
    st.s_sum  = pair_sum(s_loc);
    st.invs15 = __fdividef(1.5f, st.s_sum + 1e-10f);
    st.mse_in = 1.0f; st.mse_ad = 1.0f; st.mse_mn = 1.0f;

    st.poff[0] = f; st.poff[1] = TF + f;
    st.pmr[0] = mic_r[st.poff[0]]; st.pmi[0] = mic_i[st.poff[0]];
    st.prr[0] = ref_r[st.poff[0]]; st.pri[0] = ref_i[st.poff[0]];
    st.pmr[1] = mic_r[st.poff[1]]; st.pmi[1] = mic_i[st.poff[1]];
    st.prr[1] = ref_r[st.poff[1]]; st.pri[1] = ref_i[st.poff[1]];

    for (int n0 = 0; n0 < NF; n0 += 10) {
        // ---- per-block renorm decision (exact-skip invariant, see header) ----
        float sf_loc = 0.f;
#pragma unroll
        for (int j = 0; j < 5; ++j)
            sf_loc += st.cfr[j] * st.cfr[j] + st.cfi[j] * st.cfi[j];
        const float sf_sum = pair_sum(sf_loc);
        const bool slow = __any_sync(0xffffffffu,
                                     (st.s_sum >= 3.24f) || (sf_sum >= 3.24f));
        if (!slow) {
            run_block<false>(st, n0, f, half, writer, mtail, c0,
                             mic_r, mic_i, ref_r, ref_i, out);
        } else {
            run_block<true>(st, n0, f, half, writer, mtail, c0,
                            mic_r, mic_i, ref_r, ref_i, out);
        }
    }
}

extern "C" void kernel_launch(void* const* d_in, const int* in_sizes, int n_in,
                              void* d_out, int out_size) {
    (void)in_sizes; (void)n_in; (void)out_size;
    aec_ipnlms6<<<9, 32>>>(
        (const float*)d_in[0], (const float*)d_in[1],
        (const float*)d_in[2], (const float*)d_in[3],
        (const float*)d_in[4], (const float*)d_in[5],
        (const float*)d_in[6], (const float*)d_in[7],
        (float2*)d_out);
}